// round 1
// baseline (speedup 1.0000x reference)
#include <cuda_runtime.h>
#include <math.h>

// Problem constants
#define BSZ   4096
#define NCGC  2
#define GPB   8          // graphs (b-values) per block in main kernel

// Precomputed device-global scratch (allocation-free per harness rules)
__device__ float g_A1[7 * 128];        // masked sigmoid attention, layer 1
__device__ float g_A2[7 * 128];        // masked sigmoid attention, layer 2
__device__ float g_sup1[2 * 2 * 128];  // [c][j in {0,1}] layer-1 support rows (init nodes)
__device__ float g_sup1b[2 * 128];     // [c] layer-1 support row for step nodes
__device__ float g_p2[2 * 2 * 128];    // [c][j] layer-2 support rows for nodes 0,1
__device__ float g_table[2 * 441 * 128]; // [c][key] layer-2 support for step nodes

// ---------------------------------------------------------------------------
// Kernel A: tiny precompute (1 block, 128 threads)
// ---------------------------------------------------------------------------
__global__ void precompute_kernel(
    const float* __restrict__ init_emb,   // (2,2,48)
    const float* __restrict__ other_emb,  // (2,1,48)
    const float* __restrict__ op_embs,    // (7,48)
    const float* __restrict__ Wx,         // (48,48)
    const float* __restrict__ bx,         // (48)
    const float* __restrict__ W1,         // (48,128)
    const float* __restrict__ Wa1,        // (48,128)
    const float* __restrict__ ba1,        // (128)
    const float* __restrict__ W2,         // (128,128)
    const float* __restrict__ Wa2,        // (48,128)
    const float* __restrict__ ba2)        // (128)
{
  const int d = threadIdx.x;  // 0..127

  // Attention tables (mask op==NONE baked in as zero vector)
  for (int op = 0; op < 7; ++op) {
    float s1 = ba1[d], s2 = ba2[d];
    for (int k = 0; k < 48; ++k) {
      float e = op_embs[op * 48 + k];
      s1 += e * Wa1[k * 128 + d];
      s2 += e * Wa2[k * 128 + d];
    }
    g_A1[op * 128 + d] = (op == 0) ? 0.f : 1.f / (1.f + expf(-s1));
    g_A2[op * 128 + d] = (op == 0) ? 0.f : 1.f / (1.f + expf(-s2));
  }

  __shared__ float y0[48];
  for (int c = 0; c < 2; ++c) {
    // step-node row: other_emb @ Wx + bx, then @ W1
    if (d < 48) {
      float s = bx[d];
      for (int k = 0; k < 48; ++k) s += other_emb[c * 48 + k] * Wx[k * 48 + d];
      y0[d] = s;
    }
    __syncthreads();
    {
      float s = 0.f;
      for (int h = 0; h < 48; ++h) s += y0[h] * W1[h * 128 + d];
      g_sup1b[c * 128 + d] = s;
    }
    __syncthreads();
    // init-node rows j=0,1
    for (int j = 0; j < 2; ++j) {
      if (d < 48) {
        float t = bx[d];
        for (int k = 0; k < 48; ++k)
          t += init_emb[(c * 2 + j) * 48 + k] * Wx[k * 48 + d];
        y0[d] = t;
      }
      __syncthreads();
      float u = 0.f;
      for (int h = 0; h < 48; ++h) u += y0[h] * W1[h * 128 + d];
      g_sup1[(c * 2 + j) * 128 + d] = u;
      __syncthreads();
    }
  }

  // Layer-2 support rows for nodes 0,1 (no incoming edges => y1 = relu(sup1))
  __shared__ float rr[128];
  for (int cj = 0; cj < 4; ++cj) {
    rr[d] = fmaxf(g_sup1[cj * 128 + d], 0.f);
    __syncthreads();
    float s = 0.f;
    for (int h = 0; h < 128; ++h) s += rr[h] * W2[h * 128 + d];
    g_p2[cj * 128 + d] = s;
    __syncthreads();
  }
}

// ---------------------------------------------------------------------------
// Kernel B: build the 882-entry key -> support2 table.
// key = (op0*3 + fc0)*21 + (op1*3 + fc1), fc = min(f, 2).
// table[c][key] = relu(sup1b + A1[op0]*sup(fc0) + A1[op1]*sup(fc1)) @ W2
// ---------------------------------------------------------------------------
__global__ void table_kernel(const float* __restrict__ W2) {
  __shared__ float y1s[128];
  const int d = threadIdx.x;
  const int c = blockIdx.y;

  const float s0 = g_sup1[(c * 2 + 0) * 128 + d];
  const float s1 = g_sup1[(c * 2 + 1) * 128 + d];
  const float sb = g_sup1b[c * 128 + d];

  for (int key = blockIdx.x; key < 441; key += gridDim.x) {
    const int sA = key / 21, sB = key % 21;
    const int op0 = sA / 3, fc0 = sA % 3;
    const int op1 = sB / 3, fc1 = sB % 3;
    const float v0 = (fc0 == 0) ? s0 : (fc0 == 1) ? s1 : sb;
    const float v1 = (fc1 == 0) ? s0 : (fc1 == 1) ? s1 : sb;
    const float y =
        sb + g_A1[op0 * 128 + d] * v0 + g_A1[op1 * 128 + d] * v1;
    __syncthreads();
    y1s[d] = fmaxf(y, 0.f);
    __syncthreads();
    float acc = 0.f;
#pragma unroll 16
    for (int h = 0; h < 128; ++h)
      acc += y1s[h] * __ldg(&W2[h * 128 + d]);   // W2 L1-resident after 1st key
    g_table[(c * 441 + key) * 128 + d] = acc;
  }
}

// ---------------------------------------------------------------------------
// Kernel C: main per-graph gather + layer-2 aggregation + mean.
// grid = (BSZ/GPB, NCG), block = 128 (thread d owns feature dim d)
// ---------------------------------------------------------------------------
__global__ void gcn_main_kernel(const int* __restrict__ archs,
                                float* __restrict__ out) {
  const int d = threadIdx.x;
  const int c = blockIdx.y;

  __shared__ float sA2[7 * 128];
  __shared__ float sp2[2 * 128];
  for (int i = d; i < 7 * 128; i += 128) sA2[i] = g_A2[i];
  sp2[d]       = g_p2[(c * 2 + 0) * 128 + d];
  sp2[128 + d] = g_p2[(c * 2 + 1) * 128 + d];
  __syncthreads();

  const float* __restrict__ tab = g_table + (size_t)c * 441 * 128;
  const int b0 = blockIdx.x * GPB;

#pragma unroll
  for (int g = 0; g < GPB; ++g) {
    const int b = b0 + g;
    const int4* a = (const int4*)(archs + (size_t)(b * NCGC + c) * 16);
    const int4 fA = __ldg(a);      // f[0..3]
    const int4 fB = __ldg(a + 1);  // f[4..7]
    const int4 oA = __ldg(a + 2);  // op[0..3]
    const int4 oB = __ldg(a + 3);  // op[4..7]

    const int f0 = fA.x, f1 = fA.y, f2 = fA.z, f3 = fA.w;
    const int f4 = fB.x, f5 = fB.y, f6 = fB.z, f7 = fB.w;
    const int o0 = oA.x, o1 = oA.y, o2 = oA.z, o3 = oA.w;
    const int o4 = oB.x, o5 = oB.y, o6 = oB.z, o7 = oB.w;

    // keys for step nodes 2..5 (edges 2i, 2i+1 feed node 2+i)
    const int k0 = (o0 * 3 + min(f0, 2)) * 21 + o1 * 3 + min(f1, 2);
    const int k1 = (o2 * 3 + min(f2, 2)) * 21 + o3 * 3 + min(f3, 2);
    const int k2 = (o4 * 3 + min(f4, 2)) * 21 + o5 * 3 + min(f5, 2);
    const int k3 = (o6 * 3 + min(f6, 2)) * 21 + o7 * 3 + min(f7, 2);

    const float r0 = __ldg(&tab[k0 * 128 + d]);  // support2 of node 2
    const float r1 = __ldg(&tab[k1 * 128 + d]);  // node 3
    const float r2 = __ldg(&tab[k2 * 128 + d]);  // node 4
    const float r3 = __ldg(&tab[k3 * 128 + d]);  // node 5

    float acc = r0 + r1 + r2 + r3;

    auto src = [&](int ff) -> float {
      return ff == 0 ? sp2[d]
           : ff == 1 ? sp2[128 + d]
           : ff == 2 ? r0
           : ff == 3 ? r1
           : r2;   // ff == 4
    };

    acc += sA2[o0 * 128 + d] * src(f0);
    acc += sA2[o1 * 128 + d] * src(f1);
    acc += sA2[o2 * 128 + d] * src(f2);
    acc += sA2[o3 * 128 + d] * src(f3);
    acc += sA2[o4 * 128 + d] * src(f4);
    acc += sA2[o5 * 128 + d] * src(f5);
    acc += sA2[o6 * 128 + d] * src(f6);
    acc += sA2[o7 * 128 + d] * src(f7);

    out[(size_t)(b * NCGC + c) * 128 + d] = acc * 0.25f;
  }
}

// ---------------------------------------------------------------------------
extern "C" void kernel_launch(void* const* d_in, const int* in_sizes, int n_in,
                              void* d_out, int out_size) {
  const int*   archs     = (const int*)d_in[0];
  const float* init_emb  = (const float*)d_in[1];
  const float* other_emb = (const float*)d_in[2];
  const float* op_embs   = (const float*)d_in[3];
  const float* Wx        = (const float*)d_in[4];
  const float* bx        = (const float*)d_in[5];
  const float* W1        = (const float*)d_in[6];
  const float* Wa1       = (const float*)d_in[7];
  const float* ba1       = (const float*)d_in[8];
  const float* W2        = (const float*)d_in[9];
  const float* Wa2       = (const float*)d_in[10];
  const float* ba2       = (const float*)d_in[11];
  float* out = (float*)d_out;

  precompute_kernel<<<1, 128>>>(init_emb, other_emb, op_embs, Wx, bx, W1, Wa1,
                                ba1, W2, Wa2, ba2);
  table_kernel<<<dim3(63, 2), 128>>>(W2);
  gcn_main_kernel<<<dim3(BSZ / GPB, NCGC), 128>>>(archs, out);
}

// round 2
// speedup vs baseline: 1.1105x; 1.1105x over previous
#include <cuda_runtime.h>
#include <math.h>

// Problem constants
#define BSZ   4096
#define NCGC  2
#define GPB   8          // graphs per block in main kernel
#define KBLK  111        // key-blocks per c in build kernel (441 keys, ~4 each)

// Device-global scratch (allocation-free per harness rules)
__device__ float g_A2[7 * 128];          // masked sigmoid attention, layer 2
__device__ float g_p2[2 * 2 * 128];      // [c][j] layer-2 support rows, nodes 0,1
__device__ float g_table[2 * 441 * 128]; // [c][key] layer-2 support, step nodes

// ---------------------------------------------------------------------------
// Kernel 1: fused precompute + 882-entry table build.
// grid = (KBLK, 2), block = 128. Every block redundantly recomputes the tiny
// per-c ingredients (all weight loads L2-broadcast); block 0 also writes the
// A2 / p2 tables needed by the main kernel.
// key = (op0*3 + fc0)*21 + (op1*3 + fc1), fc = min(f, 2).
// table[c][key] = relu(sup1b + A1[op0]*sup(fc0) + A1[op1]*sup(fc1)) @ W2
// ---------------------------------------------------------------------------
__global__ void build_kernel(
    const float* __restrict__ init_emb,   // (2,2,48)
    const float* __restrict__ other_emb,  // (2,1,48)
    const float* __restrict__ op_embs,    // (7,48)
    const float* __restrict__ Wx,         // (48,48)
    const float* __restrict__ bx,         // (48)
    const float* __restrict__ W1,         // (48,128)
    const float* __restrict__ Wa1,        // (48,128)
    const float* __restrict__ ba1,        // (128)
    const float* __restrict__ W2,         // (128,128)
    const float* __restrict__ Wa2,        // (48,128)
    const float* __restrict__ ba2)        // (128)
{
  const int d = threadIdx.x;
  const int c = blockIdx.y;

  __shared__ float ope[7 * 48];
  __shared__ float sh[128];
  for (int i = d; i < 7 * 48; i += 128) ope[i] = __ldg(&op_embs[i]);
  __syncthreads();

  // Layer-1 support rows: s0,s1 = init nodes, sb = step nodes (all identical)
  float srow[3];
#pragma unroll
  for (int r = 0; r < 3; ++r) {
    const float* e = (r < 2) ? (init_emb + (c * 2 + r) * 48)
                             : (other_emb + c * 48);
    if (d < 48) {
      float t = __ldg(&bx[d]);
#pragma unroll
      for (int k = 0; k < 48; ++k) t += __ldg(&e[k]) * __ldg(&Wx[k * 48 + d]);
      sh[d] = t;
    }
    __syncthreads();
    float s = 0.f;
#pragma unroll
    for (int h = 0; h < 48; ++h) s += sh[h] * __ldg(&W1[h * 128 + d]);
    srow[r] = s;
    __syncthreads();
  }
  const float s0 = srow[0], s1 = srow[1], sb = srow[2];

  // A1 rows, per-thread registers (only own feature dim d needed)
  float a1[7];
  {
    float acc[7];
#pragma unroll
    for (int op = 0; op < 7; ++op) acc[op] = __ldg(&ba1[d]);
    for (int k = 0; k < 48; ++k) {
      const float w = __ldg(&Wa1[k * 128 + d]);
#pragma unroll
      for (int op = 0; op < 7; ++op) acc[op] += ope[op * 48 + k] * w;
    }
    a1[0] = 0.f;
#pragma unroll
    for (int op = 1; op < 7; ++op) a1[op] = 1.f / (1.f + expf(-acc[op]));
  }

  // Block 0 extras: A2 attention table + p2 rows for init nodes
  if (blockIdx.x == 0) {
    float acc[7];
#pragma unroll
    for (int op = 0; op < 7; ++op) acc[op] = __ldg(&ba2[d]);
    for (int k = 0; k < 48; ++k) {
      const float w = __ldg(&Wa2[k * 128 + d]);
#pragma unroll
      for (int op = 0; op < 7; ++op) acc[op] += ope[op * 48 + k] * w;
    }
    if (c == 0) {
      g_A2[d] = 0.f;
#pragma unroll
      for (int op = 1; op < 7; ++op)
        g_A2[op * 128 + d] = 1.f / (1.f + expf(-acc[op]));
    }
    // p2[c][j] = relu(sup1[c][j]) @ W2  (init nodes have no incoming edges)
#pragma unroll
    for (int j = 0; j < 2; ++j) {
      __syncthreads();
      sh[d] = fmaxf(j == 0 ? s0 : s1, 0.f);
      __syncthreads();
      float p = 0.f;
#pragma unroll 16
      for (int h = 0; h < 128; ++h) p += sh[h] * __ldg(&W2[h * 128 + d]);
      g_p2[(c * 2 + j) * 128 + d] = p;
    }
  }

  // Table keys
  for (int key = blockIdx.x; key < 441; key += KBLK) {
    const int sA = key / 21, sB = key % 21;
    const int op0 = sA / 3, fc0 = sA % 3;
    const int op1 = sB / 3, fc1 = sB % 3;
    const float v0 = (fc0 == 0) ? s0 : (fc0 == 1) ? s1 : sb;
    const float v1 = (fc1 == 0) ? s0 : (fc1 == 1) ? s1 : sb;
    const float y = sb + a1[op0] * v0 + a1[op1] * v1;
    __syncthreads();
    sh[d] = fmaxf(y, 0.f);
    __syncthreads();
    float acc = 0.f;
#pragma unroll 16
    for (int h = 0; h < 128; ++h) acc += sh[h] * __ldg(&W2[h * 128 + d]);
    g_table[(c * 441 + key) * 128 + d] = acc;
  }
}

// ---------------------------------------------------------------------------
// Kernel 2: main per-graph gather + layer-2 aggregation + mean.
// grid = (BSZ/GPB, NCG), block = 128 (thread d owns feature dim d)
// ---------------------------------------------------------------------------
__global__ void gcn_main_kernel(const int* __restrict__ archs,
                                float* __restrict__ out) {
  const int d = threadIdx.x;
  const int c = blockIdx.y;

  __shared__ float sA2[7 * 128];
  __shared__ float sp2[2 * 128];
  for (int i = d; i < 7 * 128; i += 128) sA2[i] = g_A2[i];
  sp2[d]       = g_p2[(c * 2 + 0) * 128 + d];
  sp2[128 + d] = g_p2[(c * 2 + 1) * 128 + d];
  __syncthreads();

  const float* __restrict__ tab = g_table + (size_t)c * 441 * 128;
  const int b0 = blockIdx.x * GPB;

#pragma unroll
  for (int g = 0; g < GPB; ++g) {
    const int b = b0 + g;
    const int4* a = (const int4*)(archs + (size_t)(b * NCGC + c) * 16);
    const int4 fA = __ldg(a);      // f[0..3]
    const int4 fB = __ldg(a + 1);  // f[4..7]
    const int4 oA = __ldg(a + 2);  // op[0..3]
    const int4 oB = __ldg(a + 3);  // op[4..7]

    const int f0 = fA.x, f1 = fA.y, f2 = fA.z, f3 = fA.w;
    const int f4 = fB.x, f5 = fB.y, f6 = fB.z, f7 = fB.w;
    const int o0 = oA.x, o1 = oA.y, o2 = oA.z, o3 = oA.w;
    const int o4 = oB.x, o5 = oB.y, o6 = oB.z, o7 = oB.w;

    // keys for step nodes 2..5 (edges 2i, 2i+1 feed node 2+i)
    const int k0 = (o0 * 3 + min(f0, 2)) * 21 + o1 * 3 + min(f1, 2);
    const int k1 = (o2 * 3 + min(f2, 2)) * 21 + o3 * 3 + min(f3, 2);
    const int k2 = (o4 * 3 + min(f4, 2)) * 21 + o5 * 3 + min(f5, 2);
    const int k3 = (o6 * 3 + min(f6, 2)) * 21 + o7 * 3 + min(f7, 2);

    const float r0 = __ldg(&tab[k0 * 128 + d]);  // support2 of node 2
    const float r1 = __ldg(&tab[k1 * 128 + d]);  // node 3
    const float r2 = __ldg(&tab[k2 * 128 + d]);  // node 4
    const float r3 = __ldg(&tab[k3 * 128 + d]);  // node 5

    float acc = r0 + r1 + r2 + r3;

    auto src = [&](int ff) -> float {
      return ff == 0 ? sp2[d]
           : ff == 1 ? sp2[128 + d]
           : ff == 2 ? r0
           : ff == 3 ? r1
           : r2;   // ff == 4
    };

    acc += sA2[o0 * 128 + d] * src(f0);
    acc += sA2[o1 * 128 + d] * src(f1);
    acc += sA2[o2 * 128 + d] * src(f2);
    acc += sA2[o3 * 128 + d] * src(f3);
    acc += sA2[o4 * 128 + d] * src(f4);
    acc += sA2[o5 * 128 + d] * src(f5);
    acc += sA2[o6 * 128 + d] * src(f6);
    acc += sA2[o7 * 128 + d] * src(f7);

    out[(size_t)(b * NCGC + c) * 128 + d] = acc * 0.25f;
  }
}

// ---------------------------------------------------------------------------
extern "C" void kernel_launch(void* const* d_in, const int* in_sizes, int n_in,
                              void* d_out, int out_size) {
  const int*   archs     = (const int*)d_in[0];
  const float* init_emb  = (const float*)d_in[1];
  const float* other_emb = (const float*)d_in[2];
  const float* op_embs   = (const float*)d_in[3];
  const float* Wx        = (const float*)d_in[4];
  const float* bx        = (const float*)d_in[5];
  const float* W1        = (const float*)d_in[6];
  const float* Wa1       = (const float*)d_in[7];
  const float* ba1       = (const float*)d_in[8];
  const float* W2        = (const float*)d_in[9];
  const float* Wa2       = (const float*)d_in[10];
  const float* ba2       = (const float*)d_in[11];
  float* out = (float*)d_out;

  build_kernel<<<dim3(KBLK, NCGC), 128>>>(init_emb, other_emb, op_embs, Wx, bx,
                                          W1, Wa1, ba1, W2, Wa2, ba2);
  gcn_main_kernel<<<dim3(BSZ / GPB, NCGC), 128>>>(archs, out);
}

// round 3
// speedup vs baseline: 2.0744x; 1.8680x over previous
#include <cuda_runtime.h>
#include <math.h>

// Problem constants
#define BSZ   4096
#define NCGC  2
#define KBLK  147        // key-blocks per c in build kernel (441 keys, 3 each)

#define MAIN_BLOCK 256   // 8 warps
#define WPB 8            // warps per block
#define GPW 2            // graphs per warp

// Device-global scratch (allocation-free per harness rules)
__device__ float g_A2[7 * 128];          // masked sigmoid attention, layer 2
__device__ float g_p2[2 * 2 * 128];      // [c][j] layer-2 support rows, nodes 0,1
__device__ float g_table[2 * 441 * 128]; // [c][key] layer-2 support, step nodes

// ---------------------------------------------------------------------------
// Kernel 1: fused precompute + 882-entry table build.
// grid = (KBLK, 2), block = 128. Every block redundantly recomputes the tiny
// per-c ingredients; block 0 also writes the A2 / p2 tables.
// key = (op0*3 + fc0)*21 + (op1*3 + fc1), fc = min(f, 2).
// table[c][key] = relu(sup1b + A1[op0]*sup(fc0) + A1[op1]*sup(fc1)) @ W2
// ---------------------------------------------------------------------------
__global__ void build_kernel(
    const float* __restrict__ init_emb,   // (2,2,48)
    const float* __restrict__ other_emb,  // (2,1,48)
    const float* __restrict__ op_embs,    // (7,48)
    const float* __restrict__ Wx,         // (48,48)
    const float* __restrict__ bx,         // (48)
    const float* __restrict__ W1,         // (48,128)
    const float* __restrict__ Wa1,        // (48,128)
    const float* __restrict__ ba1,        // (128)
    const float* __restrict__ W2,         // (128,128)
    const float* __restrict__ Wa2,        // (48,128)
    const float* __restrict__ ba2)        // (128)
{
  const int d = threadIdx.x;
  const int c = blockIdx.y;

  __shared__ float ope[7 * 48];
  __shared__ float y0[3 * 48];   // rows: 0,1 = init nodes, 2 = step node
  __shared__ float sh[128];

  for (int i = d; i < 7 * 48; i += 128) ope[i] = __ldg(&op_embs[i]);

  // One flat parallel phase for all three y0 rows (144 items over 128 threads)
  for (int it = d; it < 144; it += 128) {
    const int r = it / 48, h = it - r * 48;
    const float* e = (r < 2) ? (init_emb + (c * 2 + r) * 48)
                             : (other_emb + c * 48);
    float t = __ldg(&bx[h]);
#pragma unroll
    for (int k = 0; k < 48; ++k) t += __ldg(&e[k]) * __ldg(&Wx[k * 48 + h]);
    y0[it] = t;
  }
  __syncthreads();

  // Layer-1 support rows (shared W1-column loads across the 3 rows)
  float s0 = 0.f, s1 = 0.f, sb = 0.f;
#pragma unroll
  for (int h = 0; h < 48; ++h) {
    const float w = __ldg(&W1[h * 128 + d]);
    s0 += y0[h] * w;
    s1 += y0[48 + h] * w;
    sb += y0[96 + h] * w;
  }

  // A1 attention (this thread's feature dim only)
  float a1[7];
  {
    float acc[7];
#pragma unroll
    for (int op = 0; op < 7; ++op) acc[op] = __ldg(&ba1[d]);
    for (int k = 0; k < 48; ++k) {
      const float w = __ldg(&Wa1[k * 128 + d]);
#pragma unroll
      for (int op = 0; op < 7; ++op) acc[op] += ope[op * 48 + k] * w;
    }
    a1[0] = 0.f;
#pragma unroll
    for (int op = 1; op < 7; ++op) a1[op] = 1.f / (1.f + expf(-acc[op]));
  }

  // Block 0 extras: A2 attention table + p2 rows for init nodes
  if (blockIdx.x == 0) {
    float acc[7];
#pragma unroll
    for (int op = 0; op < 7; ++op) acc[op] = __ldg(&ba2[d]);
    for (int k = 0; k < 48; ++k) {
      const float w = __ldg(&Wa2[k * 128 + d]);
#pragma unroll
      for (int op = 0; op < 7; ++op) acc[op] += ope[op * 48 + k] * w;
    }
    if (c == 0) {
      g_A2[d] = 0.f;
#pragma unroll
      for (int op = 1; op < 7; ++op)
        g_A2[op * 128 + d] = 1.f / (1.f + expf(-acc[op]));
    }
#pragma unroll
    for (int j = 0; j < 2; ++j) {
      __syncthreads();
      sh[d] = fmaxf(j == 0 ? s0 : s1, 0.f);
      __syncthreads();
      float p0 = 0.f, p1 = 0.f, p2a = 0.f, p3 = 0.f;
#pragma unroll
      for (int h = 0; h < 128; h += 4) {
        p0 += sh[h]     * __ldg(&W2[(h)     * 128 + d]);
        p1 += sh[h + 1] * __ldg(&W2[(h + 1) * 128 + d]);
        p2a+= sh[h + 2] * __ldg(&W2[(h + 2) * 128 + d]);
        p3 += sh[h + 3] * __ldg(&W2[(h + 3) * 128 + d]);
      }
      g_p2[(c * 2 + j) * 128 + d] = (p0 + p1) + (p2a + p3);
    }
  }

  // Table keys (3 per block), 4-way-split accumulator
  for (int key = blockIdx.x; key < 441; key += KBLK) {
    const int sA = key / 21, sB = key - sA * 21;
    const int op0 = sA / 3, fc0 = sA - op0 * 3;
    const int op1 = sB / 3, fc1 = sB - op1 * 3;
    const float v0 = (fc0 == 0) ? s0 : (fc0 == 1) ? s1 : sb;
    const float v1 = (fc1 == 0) ? s0 : (fc1 == 1) ? s1 : sb;
    const float y = sb + a1[op0] * v0 + a1[op1] * v1;
    __syncthreads();
    sh[d] = fmaxf(y, 0.f);
    __syncthreads();
    float a0 = 0.f, a1_ = 0.f, a2 = 0.f, a3 = 0.f;
#pragma unroll
    for (int h = 0; h < 128; h += 4) {
      a0  += sh[h]     * __ldg(&W2[(h)     * 128 + d]);
      a1_ += sh[h + 1] * __ldg(&W2[(h + 1) * 128 + d]);
      a2  += sh[h + 2] * __ldg(&W2[(h + 2) * 128 + d]);
      a3  += sh[h + 3] * __ldg(&W2[(h + 3) * 128 + d]);
    }
    g_table[(c * 441 + key) * 128 + d] = (a0 + a1_) + (a2 + a3);
  }
}

// ---------------------------------------------------------------------------
// Kernel 2: warp-per-graph gather + layer-2 aggregation + mean.
// Each warp handles GPW graphs; each lane owns 4 feature dims (float4).
// Per-warp smem scratch rows [p2_0, p2_1, r0, r1, r2] turn the src(f)
// select chain into a single LDS.128.
// ---------------------------------------------------------------------------
__global__ void gcn_main_kernel(const int* __restrict__ archs,
                                float* __restrict__ out) {
  __shared__ __align__(16) float sA2[7 * 128];
  __shared__ float4 scratch[WPB][5 * 32];   // 5 rows x 128 floats per warp

  const int tid  = threadIdx.x;
  const int lane = tid & 31;
  const int w    = tid >> 5;

  for (int i = tid; i < 7 * 128; i += MAIN_BLOCK) sA2[i] = g_A2[i];

  const int task  = blockIdx.x * WPB + w;   // 0..4095
  const int gbase = task * GPW;             // flat graph index base
  const int c     = gbase >> 12;            // uniform within warp

  float4* scr = scratch[w];
  const float4* p2 = (const float4*)(g_p2 + c * 2 * 128);
  scr[lane]      = p2[lane];        // row 0 = node 0 support2
  scr[32 + lane] = p2[32 + lane];   // row 1 = node 1 support2
  __syncthreads();

  const float* __restrict__ tab = g_table + (size_t)c * 441 * 128;
  const float4* __restrict__ A = (const float4*)sA2;

#pragma unroll
  for (int g = 0; g < GPW; ++g) {
    const int gidx = gbase + g;
    const int b = gidx & 4095;
    const int4* a = (const int4*)(archs + (size_t)(b * NCGC + c) * 16);
    const int4 fA = __ldg(a);      // f[0..3]
    const int4 fB = __ldg(a + 1);  // f[4..7]
    const int4 oA = __ldg(a + 2);  // op[0..3]
    const int4 oB = __ldg(a + 3);  // op[4..7]

    const int k0 = (oA.x * 3 + min(fA.x, 2)) * 21 + oA.y * 3 + min(fA.y, 2);
    const int k1 = (oA.z * 3 + min(fA.z, 2)) * 21 + oA.w * 3 + min(fA.w, 2);
    const int k2 = (oB.x * 3 + min(fB.x, 2)) * 21 + oB.y * 3 + min(fB.y, 2);
    const int k3 = (oB.z * 3 + min(fB.z, 2)) * 21 + oB.w * 3 + min(fB.w, 2);

    const float4 r0 = __ldg((const float4*)(tab + k0 * 128) + lane);
    const float4 r1 = __ldg((const float4*)(tab + k1 * 128) + lane);
    const float4 r2 = __ldg((const float4*)(tab + k2 * 128) + lane);
    const float4 r3 = __ldg((const float4*)(tab + k3 * 128) + lane);

    __syncwarp();                      // WAR vs previous iteration's reads
    scr[64 + lane] = r0;               // row 2 = node 2
    scr[96 + lane] = r1;               // row 3 = node 3
    scr[128 + lane] = r2;              // row 4 = node 4
    __syncwarp();

    float4 acc;
    acc.x = (r0.x + r1.x) + (r2.x + r3.x);
    acc.y = (r0.y + r1.y) + (r2.y + r3.y);
    acc.z = (r0.z + r1.z) + (r2.z + r3.z);
    acc.w = (r0.w + r1.w) + (r2.w + r3.w);

#define EDGE(o, f)                                   \
    {                                                \
      const float4 at = A[(o) * 32 + lane];          \
      const float4 sv = scr[(f) * 32 + lane];        \
      acc.x += at.x * sv.x;                          \
      acc.y += at.y * sv.y;                          \
      acc.z += at.z * sv.z;                          \
      acc.w += at.w * sv.w;                          \
    }

    EDGE(oA.x, fA.x); EDGE(oA.y, fA.y);
    EDGE(oA.z, fA.z); EDGE(oA.w, fA.w);
    EDGE(oB.x, fB.x); EDGE(oB.y, fB.y);
    EDGE(oB.z, fB.z); EDGE(oB.w, fB.w);
#undef EDGE

    float4 res;
    res.x = acc.x * 0.25f; res.y = acc.y * 0.25f;
    res.z = acc.z * 0.25f; res.w = acc.w * 0.25f;
    ((float4*)(out + (size_t)(b * NCGC + c) * 128))[lane] = res;
  }
}

// ---------------------------------------------------------------------------
extern "C" void kernel_launch(void* const* d_in, const int* in_sizes, int n_in,
                              void* d_out, int out_size) {
  const int*   archs     = (const int*)d_in[0];
  const float* init_emb  = (const float*)d_in[1];
  const float* other_emb = (const float*)d_in[2];
  const float* op_embs   = (const float*)d_in[3];
  const float* Wx        = (const float*)d_in[4];
  const float* bx        = (const float*)d_in[5];
  const float* W1        = (const float*)d_in[6];
  const float* Wa1       = (const float*)d_in[7];
  const float* ba1       = (const float*)d_in[8];
  const float* W2        = (const float*)d_in[9];
  const float* Wa2       = (const float*)d_in[10];
  const float* ba2       = (const float*)d_in[11];
  float* out = (float*)d_out;

  build_kernel<<<dim3(KBLK, NCGC), 128>>>(init_emb, other_emb, op_embs, Wx, bx,
                                          W1, Wa1, ba1, W2, Wa2, ba2);
  const int ntask = BSZ * NCGC / GPW;        // 4096
  gcn_main_kernel<<<ntask / WPB, MAIN_BLOCK>>>(archs, out);
}

// round 4
// speedup vs baseline: 2.2821x; 1.1002x over previous
#include <cuda_runtime.h>
#include <math.h>

// Problem constants
#define BSZ   4096
#define NCGC  2

#define MAIN_BLOCK 256   // 8 warps
#define WPB 8            // warps per block
#define GPW 2            // graphs per warp

// Device-global scratch (allocation-free per harness rules)
__device__ float g_A2[7 * 128];          // masked sigmoid attention, layer 2
__device__ float g_p2[2 * 2 * 128];      // [c][j] layer-2 support rows, nodes 0,1
__device__ float g_table[2 * 441 * 128]; // [c][key] layer-2 support, step nodes

// ---------------------------------------------------------------------------
// Kernel 1: fused precompute + table build. One key per block, grid (441, 2).
// Every block redundantly recomputes the tiny per-c ingredients (weight loads
// are L2-broadcast); block x==0 also writes the A2 / p2 tables.
// key = (op0*3 + fc0)*21 + (op1*3 + fc1), fc = min(f, 2).
// table[c][key] = relu(sup1b + A1[op0]*sup(fc0) + A1[op1]*sup(fc1)) @ W2
// ---------------------------------------------------------------------------
__global__ void build_kernel(
    const float* __restrict__ init_emb,   // (2,2,48)
    const float* __restrict__ other_emb,  // (2,1,48)
    const float* __restrict__ op_embs,    // (7,48)
    const float* __restrict__ Wx,         // (48,48)
    const float* __restrict__ bx,         // (48)
    const float* __restrict__ W1,         // (48,128)
    const float* __restrict__ Wa1,        // (48,128)
    const float* __restrict__ ba1,        // (128)
    const float* __restrict__ W2,         // (128,128)
    const float* __restrict__ Wa2,        // (48,128)
    const float* __restrict__ ba2)        // (128)
{
  const int d = threadIdx.x;
  const int c = blockIdx.y;

  __shared__ float ope[7 * 48];
  __shared__ float y0[3 * 48];   // rows: 0,1 = init nodes, 2 = step node
  __shared__ float sh[128];

  for (int i = d; i < 7 * 48; i += 128) ope[i] = __ldg(&op_embs[i]);

  // One flat parallel phase for all three y0 rows (144 items over 128 threads)
  for (int it = d; it < 144; it += 128) {
    const int r = it / 48, h = it - r * 48;
    const float* e = (r < 2) ? (init_emb + (c * 2 + r) * 48)
                             : (other_emb + c * 48);
    float t = __ldg(&bx[h]);
#pragma unroll
    for (int k = 0; k < 48; ++k) t += __ldg(&e[k]) * __ldg(&Wx[k * 48 + h]);
    y0[it] = t;
  }
  __syncthreads();

  // Layer-1 support rows (shared W1-column loads across the 3 rows)
  float s0 = 0.f, s1 = 0.f, sb = 0.f;
#pragma unroll
  for (int h = 0; h < 48; ++h) {
    const float w = __ldg(&W1[h * 128 + d]);
    s0 += y0[h] * w;
    s1 += y0[48 + h] * w;
    sb += y0[96 + h] * w;
  }

  // A1 attention for this block's key ops only (op0, op1)
  const int key = blockIdx.x;
  const int sA = key / 21, sB = key - sA * 21;
  const int op0 = sA / 3, fc0 = sA - op0 * 3;
  const int op1 = sB / 3, fc1 = sB - op1 * 3;

  float a1v0, a1v1;
  {
    float acc0 = __ldg(&ba1[d]), acc1 = acc0;
#pragma unroll
    for (int k = 0; k < 48; ++k) {
      const float w = __ldg(&Wa1[k * 128 + d]);
      acc0 += ope[op0 * 48 + k] * w;
      acc1 += ope[op1 * 48 + k] * w;
    }
    a1v0 = (op0 == 0) ? 0.f : 1.f / (1.f + expf(-acc0));
    a1v1 = (op1 == 0) ? 0.f : 1.f / (1.f + expf(-acc1));
  }

  // Block 0 extras: A2 attention table + p2 rows for init nodes
  if (blockIdx.x == 0) {
    float acc[7];
#pragma unroll
    for (int op = 0; op < 7; ++op) acc[op] = __ldg(&ba2[d]);
    for (int k = 0; k < 48; ++k) {
      const float w = __ldg(&Wa2[k * 128 + d]);
#pragma unroll
      for (int op = 0; op < 7; ++op) acc[op] += ope[op * 48 + k] * w;
    }
    if (c == 0) {
      g_A2[d] = 0.f;
#pragma unroll
      for (int op = 1; op < 7; ++op)
        g_A2[op * 128 + d] = 1.f / (1.f + expf(-acc[op]));
    }
#pragma unroll
    for (int j = 0; j < 2; ++j) {
      __syncthreads();
      sh[d] = fmaxf(j == 0 ? s0 : s1, 0.f);
      __syncthreads();
      float p0 = 0.f, p1 = 0.f, p2a = 0.f, p3 = 0.f;
#pragma unroll
      for (int h = 0; h < 128; h += 4) {
        p0 += sh[h]     * __ldg(&W2[(h)     * 128 + d]);
        p1 += sh[h + 1] * __ldg(&W2[(h + 1) * 128 + d]);
        p2a+= sh[h + 2] * __ldg(&W2[(h + 2) * 128 + d]);
        p3 += sh[h + 3] * __ldg(&W2[(h + 3) * 128 + d]);
      }
      g_p2[(c * 2 + j) * 128 + d] = (p0 + p1) + (p2a + p3);
    }
  }

  // This block's single key
  {
    const float v0 = (fc0 == 0) ? s0 : (fc0 == 1) ? s1 : sb;
    const float v1 = (fc1 == 0) ? s0 : (fc1 == 1) ? s1 : sb;
    const float y = sb + a1v0 * v0 + a1v1 * v1;
    __syncthreads();
    sh[d] = fmaxf(y, 0.f);
    __syncthreads();
    float a0 = 0.f, a1_ = 0.f, a2 = 0.f, a3 = 0.f;
#pragma unroll
    for (int h = 0; h < 128; h += 4) {
      a0  += sh[h]     * __ldg(&W2[(h)     * 128 + d]);
      a1_ += sh[h + 1] * __ldg(&W2[(h + 1) * 128 + d]);
      a2  += sh[h + 2] * __ldg(&W2[(h + 2) * 128 + d]);
      a3  += sh[h + 3] * __ldg(&W2[(h + 3) * 128 + d]);
    }
    g_table[(c * 441 + key) * 128 + d] = (a0 + a1_) + (a2 + a3);
  }

#if __CUDA_ARCH__ >= 900
  cudaTriggerProgrammaticLaunchCompletion();
#endif
}

// ---------------------------------------------------------------------------
// Kernel 2 (PDL consumer): warp-per-graph gather + layer-2 agg + mean.
// All build-independent work (arch loads, key math) happens BEFORE
// cudaGridDependencySynchronize(), overlapping with build_kernel.
// ---------------------------------------------------------------------------
__global__ void gcn_main_kernel(const int* __restrict__ archs,
                                float* __restrict__ out) {
  __shared__ __align__(16) float sA2[7 * 128];
  __shared__ float4 scratch[WPB][5 * 32];   // 5 rows x 128 floats per warp

  const int tid  = threadIdx.x;
  const int lane = tid & 31;
  const int w    = tid >> 5;

  const int task  = blockIdx.x * WPB + w;   // 0..4095
  const int gbase = task * GPW;
  const int c     = gbase >> 12;            // uniform within warp

  // ---- pre-dependency phase: arch loads + key computation ----
  int4 fa[GPW], fb[GPW], oa[GPW], ob[GPW];
  int  keys[GPW][4], bb[GPW];
#pragma unroll
  for (int g = 0; g < GPW; ++g) {
    const int b = (gbase + g) & (BSZ - 1);
    bb[g] = b;
    const int4* a = (const int4*)(archs + (size_t)(b * NCGC + c) * 16);
    fa[g] = __ldg(a);      // f[0..3]
    fb[g] = __ldg(a + 1);  // f[4..7]
    oa[g] = __ldg(a + 2);  // op[0..3]
    ob[g] = __ldg(a + 3);  // op[4..7]
    keys[g][0] = (oa[g].x * 3 + min(fa[g].x, 2)) * 21 + oa[g].y * 3 + min(fa[g].y, 2);
    keys[g][1] = (oa[g].z * 3 + min(fa[g].z, 2)) * 21 + oa[g].w * 3 + min(fa[g].w, 2);
    keys[g][2] = (ob[g].x * 3 + min(fb[g].x, 2)) * 21 + ob[g].y * 3 + min(fb[g].y, 2);
    keys[g][3] = (ob[g].z * 3 + min(fb[g].z, 2)) * 21 + ob[g].w * 3 + min(fb[g].w, 2);
  }

  // ---- wait for build_kernel's writes ----
#if __CUDA_ARCH__ >= 900
  cudaGridDependencySynchronize();
#endif

  for (int i = tid; i < 7 * 128; i += MAIN_BLOCK) sA2[i] = g_A2[i];
  float4* scr = scratch[w];
  const float4* p2 = (const float4*)(g_p2 + c * 2 * 128);
  scr[lane]      = p2[lane];        // row 0 = node 0 support2
  scr[32 + lane] = p2[32 + lane];   // row 1 = node 1 support2
  __syncthreads();

  const float* __restrict__ tab = g_table + (size_t)c * 441 * 128;

  // Issue all 8 gathers up-front (MLP = 8 per warp)
  float4 r[GPW][4];
#pragma unroll
  for (int g = 0; g < GPW; ++g)
#pragma unroll
    for (int e = 0; e < 4; ++e)
      r[g][e] = __ldg((const float4*)(tab + keys[g][e] * 128) + lane);

  const float4* __restrict__ A = (const float4*)sA2;

#pragma unroll
  for (int g = 0; g < GPW; ++g) {
    __syncwarp();                  // WAR vs previous graph's scr reads
    scr[64 + lane]  = r[g][0];     // row 2 = node 2
    scr[96 + lane]  = r[g][1];     // row 3 = node 3
    scr[128 + lane] = r[g][2];     // row 4 = node 4
    __syncwarp();

    float4 acc;
    acc.x = (r[g][0].x + r[g][1].x) + (r[g][2].x + r[g][3].x);
    acc.y = (r[g][0].y + r[g][1].y) + (r[g][2].y + r[g][3].y);
    acc.z = (r[g][0].z + r[g][1].z) + (r[g][2].z + r[g][3].z);
    acc.w = (r[g][0].w + r[g][1].w) + (r[g][2].w + r[g][3].w);

#define EDGE(o, f)                                   \
    {                                                \
      const float4 at = A[(o) * 32 + lane];          \
      const float4 sv = scr[(f) * 32 + lane];        \
      acc.x += at.x * sv.x;                          \
      acc.y += at.y * sv.y;                          \
      acc.z += at.z * sv.z;                          \
      acc.w += at.w * sv.w;                          \
    }

    EDGE(oa[g].x, fa[g].x); EDGE(oa[g].y, fa[g].y);
    EDGE(oa[g].z, fa[g].z); EDGE(oa[g].w, fa[g].w);
    EDGE(ob[g].x, fb[g].x); EDGE(ob[g].y, fb[g].y);
    EDGE(ob[g].z, fb[g].z); EDGE(ob[g].w, fb[g].w);
#undef EDGE

    float4 res;
    res.x = acc.x * 0.25f; res.y = acc.y * 0.25f;
    res.z = acc.z * 0.25f; res.w = acc.w * 0.25f;
    ((float4*)(out + (size_t)(bb[g] * NCGC + c) * 128))[lane] = res;
  }
}

// ---------------------------------------------------------------------------
extern "C" void kernel_launch(void* const* d_in, const int* in_sizes, int n_in,
                              void* d_out, int out_size) {
  const int*   archs     = (const int*)d_in[0];
  const float* init_emb  = (const float*)d_in[1];
  const float* other_emb = (const float*)d_in[2];
  const float* op_embs   = (const float*)d_in[3];
  const float* Wx        = (const float*)d_in[4];
  const float* bx        = (const float*)d_in[5];
  const float* W1        = (const float*)d_in[6];
  const float* Wa1       = (const float*)d_in[7];
  const float* ba1       = (const float*)d_in[8];
  const float* W2        = (const float*)d_in[9];
  const float* Wa2       = (const float*)d_in[10];
  const float* ba2       = (const float*)d_in[11];
  float* out = (float*)d_out;

  build_kernel<<<dim3(441, NCGC), 128>>>(init_emb, other_emb, op_embs, Wx, bx,
                                         W1, Wa1, ba1, W2, Wa2, ba2);

  // Main kernel launched with Programmatic Dependent Launch: it begins while
  // build_kernel runs, and each thread blocks at cudaGridDependencySynchronize
  // until build_kernel completes.
  cudaLaunchConfig_t cfg = {};
  cfg.gridDim  = dim3(BSZ * NCGC / GPW / WPB);   // 512 blocks
  cfg.blockDim = dim3(MAIN_BLOCK);
  cudaLaunchAttribute attr[1];
  attr[0].id = cudaLaunchAttributeProgrammaticStreamSerialization;
  attr[0].val.programmaticStreamSerializationAllowed = 1;
  cfg.attrs = attr;
  cfg.numAttrs = 1;
  cudaLaunchKernelEx(&cfg, gcn_main_kernel, archs, out);
}